// round 16
// baseline (speedup 1.0000x reference)
#include <cuda_runtime.h>

#define HH 256
#define WW 256
#define MAXSLICES 64
#define TPC 16              // CTAs (16-col tiles) per slice
#define LUTCAP 2304         // floats fitting in the gs region (9216 B)

// ---- device globals (allocation-free scratch / rendezvous state) ----
__device__ unsigned g_bits[MAXSLICES * 2048];   // packed mask, 2048 words/slice
__device__ int g_ticket[MAXSLICES];             // monotonic, reset-free
__device__ int g_pmax[MAXSLICES][TPC];          // overwritten each replay

// ================= K_pre: pack mask bits (bandwidth-bound, ~2.8us) ========
__global__ void __launch_bounds__(256) k_pack(const float* __restrict__ in)
{
    const int base = blockIdx.x * 2048 + threadIdx.x;
    #pragma unroll
    for (int i = 0; i < 8; i++) {
        int n = base + i * 256;
        bool m = (in[n] != 0.0f);
        unsigned b = __ballot_sync(0xffffffffu, m);
        if ((threadIdx.x & 31) == 0) g_bits[n >> 5] = b;
    }
}

__device__ __forceinline__ void spin_until(volatile int* p, int target)
{
    while (*p < target) __nanosleep(32);
}

// ================= fused: g -> exact min-plus -> rendezvous -> LUT write ===
// CTA = (slice, 16-col tile). Mapping: cp = t&7 -> cols (2cp, 2cp+1);
// rg = t>>3 -> rows rg*8..rg*8+7.
__global__ void __launch_bounds__(256, 6)
wdt_fused(float* __restrict__ out)
{
    __shared__ unsigned       bm[HH * 9];       // 9216 B: bitmask, 9-word rows (bank-clean)
    __shared__ unsigned short gs[HH * 18];      // 9216 B: g tile; reused as sqrt-LUT
    __shared__ int   s_red;
    __shared__ int   s_m2;
    __shared__ float s_rinv;

    const int slice = blockIdx.x >> 4;
    const int ct    = blockIdx.x & 15;
    const int t     = threadIdx.x;
    float* oslab = out + (size_t)slice * (HH * WW) + ct * 16;

    if (t == 0) s_red = 0;

    // ---- phase 1: load packed bitmask, convert to 9-word row stride ----
    {
        const uint4* src4 = reinterpret_cast<const uint4*>(g_bits + slice * 2048);
        uint4 a = src4[t];
        uint4 b = src4[t + 256];
        int n0 = 4 * t;                         // words n0..n0+3: row n0>>3, col n0&7
        unsigned* d0 = bm + (n0 >> 3) * 9 + (n0 & 7);
        d0[0] = a.x; d0[1] = a.y; d0[2] = a.z; d0[3] = a.w;
        int n1 = n0 + 1024;
        unsigned* d1 = bm + (n1 >> 3) * 9 + (n1 & 7);
        d1[0] = b.x; d1[1] = b.y; d1[2] = b.z; d1[3] = b.w;
    }
    __syncthreads();

    const int cp = t & 7;                       // column pair within tile
    const int rg = t >> 3;                      // row group
    const int q0 = rg * 8;
    unsigned* gsw = reinterpret_cast<unsigned*>(gs);   // 9 words/row

    const int wi    = ct >> 1;                  // CTA-uniform word index
    const int j0    = (ct & 1) * 16 + 2 * cp;
    const int gcol0 = ct * 16 + 2 * cp;

    // ---- phase 2: branch-free funnel-shift scan; fallbacks deferred ----
    unsigned fbmask = 0;
    #pragma unroll
    for (int k = 0; k < 8; k++) {
        int r = q0 + k;
        const unsigned* row = bm + r * 9;       // conflict-free broadcasts
        unsigned cur   = row[wi];
        unsigned prevw = (wi > 0) ? row[wi - 1] : 0xffffffffu;   // outside: no zeros
        unsigned nextw = (wi < 7) ? row[wi + 1] : 0xffffffffu;

        unsigned yl0 = ~__funnelshift_rc(prevw, cur, j0 + 1);
        unsigned yr0 = ~__funnelshift_rc(cur, nextw, j0 + 1);
        unsigned yl1 = ~__funnelshift_rc(prevw, cur, j0 + 2);
        unsigned yr1 = ~__funnelshift_rc(cur, nextw, j0 + 2);
        // background pixels: yl bit31 = own bit = 0 -> clz = 0 automatically
        int g0 = min(yl0 ? __clz(yl0) : 512, yr0 ? __ffs(yr0) : 512);
        int g1 = min(yl1 ? __clz(yl1) : 512, yr1 ? __ffs(yr1) : 512);
        if (!(yl0 && yr0 && yl1 && yr1)) fbmask |= 1u << k;  // >=31-run: p ~ 2^-31
        gsw[r * 9 + cp] = (unsigned)g0 | ((unsigned)g1 << 16);
    }
    // rare exact fallback (window exceeded): full serial recompute of the row pair
    while (fbmask) {
        int k = __ffs(fbmask) - 1; fbmask &= fbmask - 1;
        int r = q0 + k;
        const unsigned* row = bm + r * 9;
        int gq[2];
        #pragma unroll
        for (int c = 0; c < 2; c++) {
            int gc = gcol0 + c;
            int gv = 0;
            if ((row[gc >> 5] >> (gc & 31)) & 1) {
                int dl = 512, dr = 512;         // BIG = H + W (reference clamp)
                for (int d = 1; d <= gc && dl == 512; d++) {
                    int cc = gc - d;
                    if (!((row[cc >> 5] >> (cc & 31)) & 1)) dl = d;
                }
                for (int d = 1; gc + d < WW && dr == 512; d++) {
                    int cc = gc + d;
                    if (!((row[cc >> 5] >> (cc & 31)) & 1)) dr = d;
                }
                gv = min(dl, dr);
            }
            gq[c] = gv;
        }
        gsw[r * 9 + cp] = (unsigned)gq[0] | ((unsigned)gq[1] << 16);
    }
    __syncthreads();

    // ---- phase 3: exact vertical min-plus, 2 cols/thread, results in regs ----
    // d2[q] = min_r' g[r']^2 + (q-r')^2; adaptive radius to max(best0,best1): exact.
    unsigned pk[8];
    int colmax = 0;
    #pragma unroll
    for (int k = 0; k < 8; k++) {
        int q = q0 + k;
        unsigned w0 = gsw[q * 9 + cp];
        int ga = w0 & 0xffffu, gb = w0 >> 16;
        int best0 = ga * ga, best1 = gb * gb;
        int bmax = max(best0, best1);
        for (int dd = 1; dd * dd < bmax; dd++) {
            int ddsq = dd * dd;
            int u = q - dd, v = q + dd;
            if (u >= 0) {
                unsigned wu = gsw[u * 9 + cp];
                int a = wu & 0xffffu, b = wu >> 16;
                best0 = min(best0, a * a + ddsq);
                best1 = min(best1, b * b + ddsq);
            }
            if (v < HH) {
                unsigned wv = gsw[v * 9 + cp];
                int a = wv & 0xffffu, b = wv >> 16;
                best0 = min(best0, a * a + ddsq);
                best1 = min(best1, b * b + ddsq);
            }
            bmax = max(best0, best1);
        }
        colmax = max(colmax, bmax);
        pk[k] = (unsigned)min(best0, 65535) | ((unsigned)min(best1, 65535) << 16);
    }

    // ---- phase 4: CTA max; then t0 rendezvous while others build sqrt-LUT ----
    #pragma unroll
    for (int off = 16; off; off >>= 1)
        colmax = max(colmax, __shfl_xor_sync(0xffffffffu, colmax, off));
    if ((t & 31) == 0) atomicMax(&s_red, colmax);
    __syncthreads();          // s_red final; all phase-3 gs reads done -> gs reusable

    const int cred = s_red;   // CTA-local d2 bound: this CTA's LUT needs 0..cred only
    float* lut = reinterpret_cast<float*>(gs);
    if (t == 0) {
        g_pmax[slice][ct] = cred;                   // plain store each replay
        __threadfence();
        int tk = atomicAdd(&g_ticket[slice], 1);    // monotonic ticket
        int target = (tk & ~(TPC - 1)) + TPC;       // my replay's group of TPC
        spin_until(&g_ticket[slice], target);
        __threadfence();
        int m2 = 0;
        #pragma unroll
        for (int i = 0; i < TPC; i++) m2 = max(m2, __ldcg(&g_pmax[slice][i]));
        s_m2 = m2;
        s_rinv = (m2 > 0) ? rsqrtf((float)m2) : 0.0f;
    } else if (cred < LUTCAP) {
        // overlap with the spin: sqrt(i) needs no global info
        for (int i = t - 1; i <= cred; i += 255)
            lut[i] = sqrtf((float)i);
    }
    __syncthreads();

    const int   m2   = s_m2;
    const float rinv = s_rinv;

    // ---- phase 5: output from regs via float2, written exactly once ----
    float2* opair = reinterpret_cast<float2*>(oslab + 2 * cp);   // 8B-aligned
    if (m2 > 0 && cred < LUTCAP) {
        #pragma unroll
        for (int k = 0; k < 8; k++) {
            unsigned w = pk[k];                 // d2 <= cred -> LUT-safe
            opair[(q0 + k) * (WW / 2)] =
                make_float2(1.0f - lut[w & 0xffffu] * rinv,
                            1.0f - lut[w >> 16] * rinv);
        }
    } else if (m2 > 0) {
        // pathological huge distances: exact per-pixel sqrt fallback
        #pragma unroll
        for (int k = 0; k < 8; k++) {
            unsigned w = pk[k];
            opair[(q0 + k) * (WW / 2)] =
                make_float2(1.0f - sqrtf((float)(w & 0xffffu)) * rinv,
                            1.0f - sqrtf((float)(w >> 16)) * rinv);
        }
    } else {
        // whole slice background: dt == 0 everywhere, reference outputs dt (= 0)
        #pragma unroll
        for (int k = 0; k < 8; k++)
            opair[(q0 + k) * (WW / 2)] = make_float2(0.0f, 0.0f);
    }
}

extern "C" void kernel_launch(void* const* d_in, const int* in_sizes, int n_in,
                              void* d_out, int out_size)
{
    const float* in = (const float*)d_in[0];
    float* out = (float*)d_out;

    int slices = in_sizes[0] / (HH * WW);   // 48 for the reference shapes
    if (slices > MAXSLICES) slices = MAXSLICES;

    // Pin max smem carveout: 6 CTAs/SM (6 x 18.4KB = 110.6KB) never smem-limited.
    cudaFuncSetAttribute(wdt_fused, cudaFuncAttributePreferredSharedMemoryCarveout, 100);

    k_pack<<<slices * 32, 256>>>(in);
    // launch_bounds(256,6): capacity 148*6 = 888 >= grid 768 -> all CTAs
    // co-resident -> the max rendezvous cannot deadlock.
    wdt_fused<<<slices * TPC, 256>>>(out);
}